// round 11
// baseline (speedup 1.0000x reference)
#include <cuda_runtime.h>
#include <cuda_bf16.h>
#include <cstdint>

// Problem constants
#define Bn 512
#define Tn 512
#define En 64
#define Hn 64
#define Gn 256   // 4*H
#define Cn 8
#define Rr 4     // batch rows per fused LSTM block
#define PF 4     // x prefetch depth (steps), power of 2
#define THR 512

typedef unsigned long long u64;

// Scratch (device globals: no cudaMalloc allowed)
__device__ float g_bufA[Bn * Tn * En];
__device__ float g_bufB[Bn * Tn * Hn];

// ---------------------------------------------------------------------------
// packed f32x2 helpers
// ---------------------------------------------------------------------------
__device__ __forceinline__ u64 pack2(float lo, float hi) {
    u64 r; asm("mov.b64 %0, {%1, %2};" : "=l"(r) : "f"(lo), "f"(hi)); return r;
}
__device__ __forceinline__ void unpack2(u64 v, float& lo, float& hi) {
    asm("mov.b64 {%0, %1}, %2;" : "=f"(lo), "=f"(hi) : "l"(v));
}
__device__ __forceinline__ u64 fma2(u64 a, u64 b, u64 c) {
    u64 d; asm("fma.rn.f32x2 %0, %1, %2, %3;" : "=l"(d) : "l"(a), "l"(b), "l"(c));
    return d;
}
__device__ __forceinline__ float hsum4(u64 a, u64 b) {
    float p, q, s, t;
    unpack2(a, p, q); unpack2(b, s, t);
    return (p + q) + (s + t);
}

__device__ __forceinline__ float sigf(float x) {
    return 1.f / (1.f + __expf(-x));
}
__device__ __forceinline__ float tanhfast(float x) {
    return 2.f / (1.f + __expf(-2.f * x)) - 1.f;
}

// ---------------------------------------------------------------------------
// Embedding
// ---------------------------------------------------------------------------
__global__ void embed_kernel(const int* __restrict__ ids,
                             const float* __restrict__ wt,
                             const float* __restrict__ pt,
                             float* __restrict__ out)
{
    int i = blockIdx.x * blockDim.x + threadIdx.x;
    int bt = i >> 4;
    int v  = i & 15;
    int id = ids[bt];
    int t  = bt & (Tn - 1);
    float4 a = ((const float4*)wt)[id * 16 + v];
    float4 p = ((const float4*)pt)[t * 16 + v];
    float4 r;
    r.x = a.x + p.x; r.y = a.y + p.y; r.z = a.z + p.z; r.w = a.w + p.w;
    ((float4*)out)[i] = r;
}

// ---------------------------------------------------------------------------
// Fused LSTM layer: z_t = [x_t | h] @ [Wx; Wh] + b, gates, h/c update.
// No xw intermediate (removes 512 MB of DRAM round-trip per layer).
//
// 128 blocks x 512 threads; block owns Rr=4 batch rows for all T steps.
// Thread (kq = tid&3, jj = tid>>2 in [0,128)): columns (jj, jj+128) over
// K-quarter kq*32..+32 of the concatenated K=128 dim.
//   kq 0,1 -> x part (smem prefetch ring), kq 2,3 -> h part (hs).
// 64 weight floats/thread (32 u64). Quad shfl_xor(1,2) reduces K-partials.
// Gate phase: tid<256 (r = tid>>6, hh = tid&63); threads [256,320) store
// the prefetched x_{t+PF} float4 into the ring during the gate phase.
// ---------------------------------------------------------------------------
__global__ void __launch_bounds__(THR, 1)
fused_lstm_kernel(const float* __restrict__ xin,   // [B*T, 64]
                  const float* __restrict__ Wx,    // [64, 256]
                  const float* __restrict__ Wh,    // [64, 256]
                  const float* __restrict__ bias,  // [256]
                  float* __restrict__ hout)        // [B*T, 64]
{
    const int tid = threadIdx.x;
    const int kq  = tid & 3;
    const int jj  = (tid >> 2) & 127;
    const int b0  = blockIdx.x * Rr;

    __shared__ __align__(16) float hs[Rr][Hn];
    __shared__ __align__(16) float xsr[PF][Rr][Hn];   // x_t ring
    __shared__ float zs[Rr][Gn];

    // weights: k-quarter kq maps to Wx rows (kq<2) or Wh rows (kq>=2)
    const float* Wsrc = (kq < 2) ? (Wx + (size_t)(kq * 32) * Gn)
                                 : (Wh + (size_t)((kq - 2) * 32) * Gn);
    u64 wp0[16], wp1[16];
#pragma unroll
    for (int m = 0; m < 16; m++) {
        wp0[m] = pack2(Wsrc[(2 * m) * Gn + jj],       Wsrc[(2 * m + 1) * Gn + jj]);
        wp1[m] = pack2(Wsrc[(2 * m) * Gn + jj + 128], Wsrc[(2 * m + 1) * Gn + jj + 128]);
    }
    const float bj0 = bias[jj];
    const float bj1 = bias[jj + 128];

    // init h state
    if (tid < Rr * Hn) ((float*)hs)[tid] = 0.f;

    // prime the ring with x[t=0..PF-1]: 256 threads x 1 float4 each
    if (tid < 256) {
        int slot = tid >> 6;         // 0..3
        int r    = (tid >> 4) & 3;   // 0..3
        int v    = tid & 15;         // 0..15
        ((float4*)&xsr[slot][r][0])[v] =
            ((const float4*)(xin + ((size_t)(b0 + r) * Tn + slot) * En))[v];
    }

    const int rp = tid >> 6;         // gate row (valid tid<256)
    const int hh = tid & 63;         // gate hidden index
    float c = 0.f;
    float* hrow = hout + (size_t)(b0 + (rp & 3)) * Tn * Hn + hh;

    const bool isloader = (tid >= 256 && tid < 320);
    const int lr = (tid >> 4) & 3;   // loader row   (tid 256..319 -> 0..3)
    const int lv = tid & 15;         // loader float4 idx

    __syncthreads();

    float4 xpref = make_float4(0.f, 0.f, 0.f, 0.f);

    for (int t = 0; t < Tn; t++) {
        const int slot = t & (PF - 1);

        // issue LDG for x[t+PF] early; STS deferred to gate phase
        if (isloader && t + PF < Tn)
            xpref = ((const float4*)(xin + ((size_t)(b0 + lr) * Tn + t + PF) * En))[lv];

        // ---- dot phase: partial z over this thread's K-quarter ----
        float s0v[Rr], s1v[Rr];
#pragma unroll
        for (int r = 0; r < Rr; r++) {
            const float* vb = (kq < 2) ? &xsr[slot][r][kq * 32]
                                       : &hs[r][(kq - 2) * 32];
            const ulonglong2* v2 = (const ulonglong2*)vb;
            u64 a0 = 0ull, a1 = 0ull, d0 = 0ull, d1 = 0ull;
#pragma unroll
            for (int kv = 0; kv < 8; kv++) {
                ulonglong2 v = v2[kv];
                a0 = fma2(wp0[2 * kv],     v.x, a0);
                a1 = fma2(wp0[2 * kv + 1], v.y, a1);
                d0 = fma2(wp1[2 * kv],     v.x, d0);
                d1 = fma2(wp1[2 * kv + 1], v.y, d1);
            }
            s0v[r] = hsum4(a0, a1);
            s1v[r] = hsum4(d0, d1);
        }
        // quad reduction across the 4 K-quarters (lanes 4q..4q+3 share jj)
#pragma unroll
        for (int r = 0; r < Rr; r++) {
            float s0 = s0v[r], s1 = s1v[r];
            s0 += __shfl_xor_sync(0xFFFFFFFFu, s0, 1);
            s0 += __shfl_xor_sync(0xFFFFFFFFu, s0, 2);
            s1 += __shfl_xor_sync(0xFFFFFFFFu, s1, 1);
            s1 += __shfl_xor_sync(0xFFFFFFFFu, s1, 2);
            if (kq == 0)      zs[r][jj]       = s0 + bj0;
            else if (kq == 1) zs[r][jj + 128] = s1 + bj1;
        }
        __syncthreads();

        // ---- gate phase (tid<256) | x prefetch STS (tid 256..319) ----
        if (tid < 256) {
            float zi = zs[rp][hh];
            float zf = zs[rp][64  + hh];
            float zg = zs[rp][128 + hh];
            float zo = zs[rp][192 + hh];
            float ig = sigf(zi);
            float fg = sigf(zf);
            float gg = tanhfast(zg);
            float og = sigf(zo);
            c = fg * c + ig * gg;
            float h = og * tanhfast(c);
            hs[rp][hh] = h;
            hrow[(size_t)t * Hn] = h;
        } else if (isloader && t + PF < Tn) {
            // slot (t+PF)&(PF-1) == slot: just freed by this step's dot reads
            ((float4*)&xsr[slot][lr][0])[lv] = xpref;
        }
        __syncthreads();
    }
}

// ---------------------------------------------------------------------------
// Logits + softmax, duplicated into both time halves (bwd == fwd).
// ---------------------------------------------------------------------------
__global__ void __launch_bounds__(256)
logits_kernel(const float* __restrict__ Hs,
              const float* __restrict__ Wd,
              const float* __restrict__ bd,
              float* __restrict__ out)
{
    __shared__ float wd_s[Hn * Cn];
    __shared__ float bd_s[Cn];
    const int tid = threadIdx.x;
    for (int i = tid; i < Hn * Cn; i += 256) wd_s[i] = Wd[i];
    if (tid < Cn) bd_s[tid] = bd[tid];
    __syncthreads();

    const int row = blockIdx.x * 256 + tid;
    float acc[Cn];
#pragma unroll
    for (int cc = 0; cc < Cn; cc++) acc[cc] = bd_s[cc];

    const float4* hr = (const float4*)(Hs + (size_t)row * Hn);
#pragma unroll
    for (int kv = 0; kv < 16; kv++) {
        float4 x = hr[kv];
#pragma unroll
        for (int cc = 0; cc < Cn; cc++) {
            acc[cc] += x.x * wd_s[(4*kv+0) * Cn + cc];
            acc[cc] += x.y * wd_s[(4*kv+1) * Cn + cc];
            acc[cc] += x.z * wd_s[(4*kv+2) * Cn + cc];
            acc[cc] += x.w * wd_s[(4*kv+3) * Cn + cc];
        }
    }

    float m = acc[0];
#pragma unroll
    for (int cc = 1; cc < Cn; cc++) m = fmaxf(m, acc[cc]);
    float s = 0.f;
    float e[Cn];
#pragma unroll
    for (int cc = 0; cc < Cn; cc++) { e[cc] = __expf(acc[cc] - m); s += e[cc]; }
    float inv = 1.f / s;

    const int b = row >> 9;
    const int t = row & (Tn - 1);
    float4 r0, r1;
    r0.x = e[0]*inv; r0.y = e[1]*inv; r0.z = e[2]*inv; r0.w = e[3]*inv;
    r1.x = e[4]*inv; r1.y = e[5]*inv; r1.z = e[6]*inv; r1.w = e[7]*inv;

    float* o1 = out + ((size_t)b * (2 * Tn) + t) * Cn;
    float* o2 = o1 + (size_t)Tn * Cn;
    ((float4*)o1)[0] = r0; ((float4*)o1)[1] = r1;
    ((float4*)o2)[0] = r0; ((float4*)o2)[1] = r1;
}

// ---------------------------------------------------------------------------
// Launch
// ---------------------------------------------------------------------------
extern "C" void kernel_launch(void* const* d_in, const int* in_sizes, int n_in,
                              void* d_out, int out_size)
{
    const int*   ids        = (const int*)d_in[0];
    const float* word_table = (const float*)d_in[3];
    const float* pos_table  = (const float*)d_in[4];
    const float* Wx         = (const float*)d_in[5];
    const float* Wh         = (const float*)d_in[6];
    const float* b          = (const float*)d_in[7];
    const float* Wd         = (const float*)d_in[8];
    const float* bd         = (const float*)d_in[9];
    float* out = (float*)d_out;

    float *bufA, *bufB;
    cudaGetSymbolAddress((void**)&bufA, g_bufA);
    cudaGetSymbolAddress((void**)&bufB, g_bufB);

    // embedding -> bufA
    embed_kernel<<<(Bn * Tn * 16) / 256, 256>>>(ids, word_table, pos_table, bufA);

    // layer 1 fused (x from bufA, h -> bufB)
    fused_lstm_kernel<<<Bn / Rr, THR>>>(bufA, Wx, Wh, b, bufB);

    // layer 2 fused (x from bufB, h -> bufA)
    fused_lstm_kernel<<<Bn / Rr, THR>>>(bufB, Wx, Wh, b, bufA);

    // classifier + softmax
    logits_kernel<<<(Bn * Tn) / 256, 256>>>(bufA, Wd, bd, out);
}